// round 15
// baseline (speedup 1.0000x reference)
#include <cuda_runtime.h>
#include <cuda_fp16.h>
#include <cstdint>

#define N_NODES   50000
#define NUM_FEAT  64
#define HIDDEN    512
#define N_EDGES   800000
#define BN_EPS    1e-5f
#define MBLKS     782                   // ceil(50000/64)

// ================= helpers =================
__device__ __forceinline__ uint32_t smem_u32(const void* p) {
    uint32_t a;
    asm("{ .reg .u64 t; cvta.to.shared.u64 t, %1; cvt.u32.u64 %0, t; }" : "=r"(a) : "l"(p));
    return a;
}
__device__ __forceinline__ uint32_t pack_h2(float lo, float hi) {
    __half2 h = __floats2half2_rn(lo, hi);
    return *reinterpret_cast<uint32_t*>(&h);
}
__device__ __forceinline__ void mma_f16(float* d, const uint32_t* a, const uint32_t* b) {
    asm volatile("mma.sync.aligned.m16n8k16.row.col.f32.f16.f16.f32 "
        "{%0,%1,%2,%3}, {%4,%5,%6,%7}, {%8,%9}, {%0,%1,%2,%3};"
        : "+f"(d[0]), "+f"(d[1]), "+f"(d[2]), "+f"(d[3])
        : "r"(a[0]), "r"(a[1]), "r"(a[2]), "r"(a[3]), "r"(b[0]), "r"(b[1]));
}
__device__ __forceinline__ void cp_async16(uint32_t dst, const void* src, int src_bytes) {
    asm volatile("cp.async.cg.shared.global [%0], [%1], 16, %2;"
                 :: "r"(dst), "l"(src), "r"(src_bytes) : "memory");
}
#define CP_COMMIT() asm volatile("cp.async.commit_group;" ::: "memory")

// ================= scratch (static device globals) =================
__device__ float g_agg[(size_t)N_NODES * NUM_FEAT];        // 12.8 MB fp32
__device__ uint4 g_h1f[(size_t)MBLKS * 16 * 256];          // 51.2 MB fp16 A-fragments
__device__ float g_h2 [(size_t)N_NODES * HIDDEN];          // 102.4 MB row-major fp32
__device__ uint4 g_w1f[4 * 2 * 512];                       // W1 fp16 B-fragments
__device__ uint4 g_w2f[4 * 16 * 512];                      // W2 fp16 B-fragments
__device__ float g_sum  [HIDDEN];
__device__ float g_sumsq[HIDDEN];
__device__ float g_scale[HIDDEN];
__device__ float g_shift[HIDDEN];
__device__ int   g_idx64;
// CSR aggregation scratch
__device__ int g_cnt[N_NODES];
__device__ int g_off[N_NODES + 1];
__device__ int g_pos[N_NODES];
__device__ int g_csr[N_EDGES];

// ================= edge index fetch (dtype-flexible) =================
__device__ __forceinline__ void load_edge(const void* ei_raw, int e, int& src, int& dst) {
    if (g_idx64) {
        const long long* ei = (const long long*)ei_raw;
        src = (int)ei[e];
        dst = (int)ei[N_EDGES + e];
    } else {
        const int* ei = (const int*)ei_raw;
        src = ei[e];
        dst = ei[N_EDGES + e];
    }
}

// ================= init: zero counts + BN sums, detect ei dtype =================
__global__ void init_kernel(const long long* __restrict__ ei) {
    int i = blockIdx.x * blockDim.x + threadIdx.x;
    if (i < N_NODES) g_cnt[i] = 0;
    if (i < HIDDEN) { g_sum[i] = 0.f; g_sumsq[i] = 0.f; }
    if (i == 0) {
        int is64 = 1;
        for (int k = 0; k < 64; k++) {
            long long v = ei[k];
            if (v < 0 || v >= N_NODES) { is64 = 0; break; }
        }
        g_idx64 = is64;
    }
}

// ================= CSR build =================
__global__ void count_kernel(const void* __restrict__ ei_raw) {
    int e = blockIdx.x * blockDim.x + threadIdx.x;
    int src, dst;
    load_edge(ei_raw, e, src, dst);
    if ((unsigned)src >= N_NODES || (unsigned)dst >= N_NODES) return;
    atomicAdd(&g_cnt[dst], 1);
}

#define SCAN_T 1024
#define SCAN_CHUNK 49            // 1024*49 = 50176 >= 50000
__global__ void scan_kernel() {
    __shared__ int sums[SCAN_T];
    int t = threadIdx.x;
    int base = t * SCAN_CHUNK;
    int local = 0;
    for (int j = 0; j < SCAN_CHUNK; j++) {
        int idx = base + j;
        if (idx < N_NODES) local += g_cnt[idx];
    }
    sums[t] = local;
    __syncthreads();
    for (int off = 1; off < SCAN_T; off <<= 1) {
        int u = (t >= off) ? sums[t - off] : 0;
        __syncthreads();
        sums[t] += u;
        __syncthreads();
    }
    int running = sums[t] - local;
    for (int j = 0; j < SCAN_CHUNK; j++) {
        int idx = base + j;
        if (idx < N_NODES) {
            int c = g_cnt[idx];
            g_off[idx] = running;
            g_pos[idx] = running;
            running += c;
        }
    }
    if (t == SCAN_T - 1) g_off[N_NODES] = sums[SCAN_T - 1];
}

__global__ void fill_kernel(const void* __restrict__ ei_raw) {
    int e = blockIdx.x * blockDim.x + threadIdx.x;
    int src, dst;
    load_edge(ei_raw, e, src, dst);
    if ((unsigned)src >= N_NODES || (unsigned)dst >= N_NODES) return;
    int p = atomicAdd(&g_pos[dst], 1);
    g_csr[p] = src;
}

// ================= gather: agg[i] = x[i] + sum_{j->i} x[j] (no float atomics) ==
__global__ __launch_bounds__(256)
void gather_kernel(const float* __restrict__ x) {
    int warp = threadIdx.x >> 5, lane = threadIdx.x & 31;
    int row = blockIdx.x * 8 + warp;                  // 6250 blocks, exact
    int beg = g_off[row], end = g_off[row + 1];
    float2 acc = *(const float2*)&x[(size_t)row * NUM_FEAT + lane * 2];
    for (int n = beg; n < end; n++) {
        int s = g_csr[n];
        float2 v = *(const float2*)&x[(size_t)s * NUM_FEAT + lane * 2];
        acc.x += v.x;
        acc.y += v.y;
    }
    *(float2*)&g_agg[(size_t)row * NUM_FEAT + lane * 2] = acc;
}

// ================= weights -> fp16 B-fragment layout =================
template<int KR>
__device__ __forceinline__ void tr_one(const float* __restrict__ W, uint4* dst, int g) {
    constexpr int S = KR / 32;
    int nb = g / (S * 512);
    int rem = g % (S * 512);
    int stage = rem >> 9;
    int i4 = rem & 511;
    int lane = i4 & 31, nip = (i4 >> 5) & 3, wn = (i4 >> 7) & 1, kk = (i4 >> 8) & 1;
    int colx = nb * 128 + wn * 64 + nip * 16 + (lane >> 2);
    int colz = colx + 8;
    int kc = stage * 32 + kk * 16 + (lane & 3) * 2;
    uint4 v;
    v.x = pack_h2(W[(size_t)kc * HIDDEN + colx],       W[(size_t)(kc + 1) * HIDDEN + colx]);
    v.y = pack_h2(W[(size_t)(kc + 8) * HIDDEN + colx], W[(size_t)(kc + 9) * HIDDEN + colx]);
    v.z = pack_h2(W[(size_t)kc * HIDDEN + colz],       W[(size_t)(kc + 1) * HIDDEN + colz]);
    v.w = pack_h2(W[(size_t)(kc + 8) * HIDDEN + colz], W[(size_t)(kc + 9) * HIDDEN + colz]);
    dst[g] = v;
}
#define W1_F4 (4 * 2 * 512)            // 4096
#define W2_F4 (4 * 16 * 512)           // 32768
__global__ void tr_both_kernel(const float* __restrict__ W1, const float* __restrict__ W2) {
    int g = blockIdx.x * 256 + threadIdx.x;
    if (g < W1_F4) tr_one<NUM_FEAT>(W1, g_w1f, g);
    else           tr_one<HIDDEN>(W2, g_w2f, g - W1_F4);
}

// ================= fp16 mma.sync GEMM (R12 config) =================
// MODE 0: h1(frag fp16) = relu(g_agg(fp32) @ W1 + b1)
// MODE 1: h2(fp32 rowmaj) = h1(frag) @ W2 + b2  + fused BN column stats
// Block 64x128, BK=32 (2 x k16), 4 warps (2Mx2N) of 32x64, 3-stage cp.async.
#define ABUF 2048                       // floats per A stage (8 KB; MODE1 uses 4 KB)
#define BBUF_U4 512                     // uint4 per B stage (8 KB)
#define SMEM_GEMM_BYTES (3 * ABUF * 4 + 3 * BBUF_U4 * 16)   // 49152

template<int MODE>
__global__ __launch_bounds__(128, 4)
void gemm_mma_kernel(const float* __restrict__ bias) {
    constexpr int M = N_NODES;
    constexpr int K = (MODE == 0) ? NUM_FEAT : HIDDEN;
    constexpr int S = K / 32;           // 2 or 16

    extern __shared__ float sm[];
    float* Asm  = sm;                            // 3 x 8 KB
    uint4* Bsm  = (uint4*)(sm + 3 * ABUF);       // 3 x 512 uint4

    const int tid  = threadIdx.x;
    const int lane = tid & 31;
    const int wid  = tid >> 5;
    const int wm   = wid >> 1;       // 0..1
    const int wn   = wid & 1;        // 0..1
    const int mblk = blockIdx.x;
    const int m0   = mblk * 64;
    const int nb   = blockIdx.y;

    auto issue = [&](int s) {
        const int buf = s % 3;
        if (MODE == 0) {
            float* Ab = Asm + buf * ABUF;
            const int k0 = s * 32;
            #pragma unroll
            for (int i = 0; i < 4; i++) {
                int idx = tid + i * 128;
                int r = idx >> 3, g4 = idx & 7;
                int row = m0 + r;
                bool v = row < M;
                long long rc = v ? row : (M - 1);
                int sg = (g4 ^ (r & 7)) << 2;
                cp_async16(smem_u32(&Ab[r * 32 + sg]), &g_agg[rc * (long long)K + k0 + g4 * 4], v ? 16 : 0);
            }
        } else {
            uint4* Ab = (uint4*)(Asm + buf * ABUF);       // 256 uint4
            const uint4* asrc = g_h1f + ((size_t)mblk * 16 + s) * 256;
            #pragma unroll
            for (int i = 0; i < 2; i++) {
                int idx = tid + i * 128;
                cp_async16(smem_u32(&Ab[idx]), asrc + idx, 16);
            }
        }
        uint4* Bb = Bsm + buf * BBUF_U4;
        const uint4* src = ((MODE == 0) ? g_w1f : g_w2f) + ((size_t)nb * S + s) * BBUF_U4;
        #pragma unroll
        for (int i = 0; i < 4; i++) {
            int idx = tid + i * 128;
            cp_async16(smem_u32(&Bb[idx]), src + idx, 16);
        }
        CP_COMMIT();
    };

    float acc[2][8][4];
    #pragma unroll
    for (int mi = 0; mi < 2; mi++)
        #pragma unroll
        for (int ni = 0; ni < 8; ni++)
            #pragma unroll
            for (int j = 0; j < 4; j++) acc[mi][ni][j] = 0.f;

    issue(0);
    if (S > 1) issue(1);

    #pragma unroll 1
    for (int s = 0; s < S; s++) {
        if (s + 1 < S) asm volatile("cp.async.wait_group 1;" ::: "memory");
        else           asm volatile("cp.async.wait_group 0;" ::: "memory");
        __syncthreads();
        const int buf = s % 3;
        const float* Abf = Asm + buf * ABUF;
        const uint4* Ab4 = (const uint4*)Abf;
        const uint4* Bb  = Bsm + buf * BBUF_U4;

        #pragma unroll
        for (int kk = 0; kk < 2; kk++) {
            uint32_t a[2][4];
            if (MODE == 0) {
                const int kcl = kk * 16 + (lane & 3) * 2;
                const int g4a = kcl >> 2, offa = kcl & 3;
                const int g4b = (kcl + 8) >> 2, offb = (kcl + 8) & 3;
                #pragma unroll
                for (int mi = 0; mi < 2; mi++) {
                    int r  = wm * 32 + mi * 16 + (lane >> 2);
                    int sw = r & 7;
                    float2 f0 = *(const float2*)&Abf[r * 32 + ((g4a ^ sw) << 2) + offa];
                    float2 f1 = *(const float2*)&Abf[(r + 8) * 32 + ((g4a ^ sw) << 2) + offa];
                    float2 f2 = *(const float2*)&Abf[r * 32 + ((g4b ^ sw) << 2) + offb];
                    float2 f3 = *(const float2*)&Abf[(r + 8) * 32 + ((g4b ^ sw) << 2) + offb];
                    a[mi][0] = pack_h2(f0.x, f0.y);
                    a[mi][1] = pack_h2(f1.x, f1.y);
                    a[mi][2] = pack_h2(f2.x, f2.y);
                    a[mi][3] = pack_h2(f3.x, f3.y);
                }
            } else {
                #pragma unroll
                for (int mi = 0; mi < 2; mi++) {
                    int grp = wm * 2 + mi;
                    uint4 av = Ab4[(kk * 4 + grp) * 32 + lane];
                    a[mi][0] = av.x; a[mi][1] = av.y; a[mi][2] = av.z; a[mi][3] = av.w;
                }
            }
            uint32_t b[8][2];
            #pragma unroll
            for (int nip = 0; nip < 4; nip++) {
                uint4 bv = Bb[((kk * 2 + wn) * 4 + nip) * 32 + lane];
                b[nip * 2][0]     = bv.x;  b[nip * 2][1]     = bv.y;
                b[nip * 2 + 1][0] = bv.z;  b[nip * 2 + 1][1] = bv.w;
            }
            #pragma unroll
            for (int mi = 0; mi < 2; mi++)
                #pragma unroll
                for (int ni = 0; ni < 8; ni++)
                    mma_f16(acc[mi][ni], a[mi], b[ni]);
        }
        if (s + 2 < S) issue(s + 2);
    }

    const int n0 = nb * 128;

    if (MODE == 0) {
        // ---- epilogue: bias+relu -> fp16 A-fragments, direct from registers ----
        #pragma unroll
        for (int mi = 0; mi < 2; mi++) {
            const int grp = wm * 2 + mi;
            #pragma unroll
            for (int j = 0; j < 4; j++) {
                const int c0 = wn * 64 + (2 * j) * 8 + (lane & 3) * 2;
                const float bx0 = __ldg(&bias[n0 + c0]);
                const float by0 = __ldg(&bias[n0 + c0 + 1]);
                const float bx1 = __ldg(&bias[n0 + c0 + 8]);
                const float by1 = __ldg(&bias[n0 + c0 + 9]);
                uint4 v;
                v.x = pack_h2(fmaxf(acc[mi][2 * j][0] + bx0, 0.f),
                              fmaxf(acc[mi][2 * j][1] + by0, 0.f));
                v.y = pack_h2(fmaxf(acc[mi][2 * j][2] + bx0, 0.f),
                              fmaxf(acc[mi][2 * j][3] + by0, 0.f));
                v.z = pack_h2(fmaxf(acc[mi][2 * j + 1][0] + bx1, 0.f),
                              fmaxf(acc[mi][2 * j + 1][1] + by1, 0.f));
                v.w = pack_h2(fmaxf(acc[mi][2 * j + 1][2] + bx1, 0.f),
                              fmaxf(acc[mi][2 * j + 1][3] + by1, 0.f));
                const int sl = wn * 2 + (j >> 1);
                const int kkd = j & 1;
                g_h1f[((size_t)mblk * 16 + nb * 4 + sl) * 256 + (kkd * 4 + grp) * 32 + lane] = v;
            }
        }
    } else {
        // ---- epilogue: bias -> row-major fp32 h2 + fused BN column stats ----
        float scv[16], sqv[16];
        #pragma unroll
        for (int i = 0; i < 16; i++) { scv[i] = 0.f; sqv[i] = 0.f; }
        #pragma unroll
        for (int mi = 0; mi < 2; mi++) {
            const int r0 = m0 + wm * 32 + mi * 16 + (lane >> 2);
            #pragma unroll
            for (int ni = 0; ni < 8; ni++) {
                const int col = n0 + wn * 64 + ni * 8 + (lane & 3) * 2;
                const float bx = __ldg(&bias[col]);
                const float by = __ldg(&bias[col + 1]);
                float2 v;
                if (r0 < M) {
                    v.x = acc[mi][ni][0] + bx;
                    v.y = acc[mi][ni][1] + by;
                    scv[ni * 2]     += v.x;  sqv[ni * 2]     = fmaf(v.x, v.x, sqv[ni * 2]);
                    scv[ni * 2 + 1] += v.y;  sqv[ni * 2 + 1] = fmaf(v.y, v.y, sqv[ni * 2 + 1]);
                    *(float2*)&g_h2[(size_t)r0 * HIDDEN + col] = v;
                }
                if (r0 + 8 < M) {
                    v.x = acc[mi][ni][2] + bx;
                    v.y = acc[mi][ni][3] + by;
                    scv[ni * 2]     += v.x;  sqv[ni * 2]     = fmaf(v.x, v.x, sqv[ni * 2]);
                    scv[ni * 2 + 1] += v.y;  sqv[ni * 2 + 1] = fmaf(v.y, v.y, sqv[ni * 2 + 1]);
                    *(float2*)&g_h2[(size_t)(r0 + 8) * HIDDEN + col] = v;
                }
            }
        }
        #pragma unroll
        for (int i = 0; i < 16; i++) {
            #pragma unroll
            for (int off = 16; off >= 4; off >>= 1) {
                scv[i] += __shfl_down_sync(0xFFFFFFFFu, scv[i], off);
                sqv[i] += __shfl_down_sync(0xFFFFFFFFu, sqv[i], off);
            }
        }
        if (lane < 4) {
            #pragma unroll
            for (int i = 0; i < 16; i++) {
                int col = n0 + wn * 64 + (i >> 1) * 8 + lane * 2 + (i & 1);
                atomicAdd(&g_sum[col], scv[i]);
                atomicAdd(&g_sumsq[col], sqv[i]);
            }
        }
    }
}

// ================= BN finalize =================
__global__ void bn_finalize_kernel(const float* __restrict__ gamma,
                                   const float* __restrict__ beta) {
    int c = threadIdx.x;
    float inv_n = 1.0f / (float)N_NODES;
    float mean = g_sum[c] * inv_n;
    float var  = g_sumsq[c] * inv_n - mean * mean;
    float sc   = gamma[c] * rsqrtf(var + BN_EPS);
    g_scale[c] = sc;
    g_shift[c] = beta[c] - mean * sc;
}

// ================= fused BN-apply + ReLU + classifier =================
__global__ __launch_bounds__(256)
void cls_kernel(const float* __restrict__ Wc, const float* __restrict__ bc,
                float* __restrict__ out) {
    __shared__ float s_scale[HIDDEN], s_shift[HIDDEN], s_w0[HIDDEN], s_w1[HIDDEN];
    int tid = threadIdx.x;
    for (int c = tid; c < HIDDEN; c += 256) {
        s_scale[c] = g_scale[c];
        s_shift[c] = g_shift[c];
        s_w0[c] = Wc[c * 2 + 0];
        s_w1[c] = Wc[c * 2 + 1];
    }
    __syncthreads();

    int warp = tid >> 5, lane = tid & 31;
    int row = blockIdx.x * 8 + warp;
    const float4* h = (const float4*)&g_h2[(long long)row * HIDDEN];
    float a0 = 0.f, a1 = 0.f;
    #pragma unroll
    for (int it = 0; it < 4; it++) {
        int c4 = it * 32 + lane;
        float4 v = h[c4];
        int c = c4 * 4;
        float t;
        t = fmaxf(fmaf(v.x, s_scale[c + 0], s_shift[c + 0]), 0.f);
        a0 = fmaf(t, s_w0[c + 0], a0); a1 = fmaf(t, s_w1[c + 0], a1);
        t = fmaxf(fmaf(v.y, s_scale[c + 1], s_shift[c + 1]), 0.f);
        a0 = fmaf(t, s_w0[c + 1], a0); a1 = fmaf(t, s_w1[c + 1], a1);
        t = fmaxf(fmaf(v.z, s_scale[c + 2], s_shift[c + 2]), 0.f);
        a0 = fmaf(t, s_w0[c + 2], a0); a1 = fmaf(t, s_w1[c + 2], a1);
        t = fmaxf(fmaf(v.w, s_scale[c + 3], s_shift[c + 3]), 0.f);
        a0 = fmaf(t, s_w0[c + 3], a0); a1 = fmaf(t, s_w1[c + 3], a1);
    }
    #pragma unroll
    for (int o = 16; o > 0; o >>= 1) {
        a0 += __shfl_down_sync(0xFFFFFFFFu, a0, o);
        a1 += __shfl_down_sync(0xFFFFFFFFu, a1, o);
    }
    if (lane == 0) {
        out[row * 2 + 0] = a0 + bc[0];
        out[row * 2 + 1] = a1 + bc[1];
    }
}

// ================= launch =================
extern "C" void kernel_launch(void* const* d_in, const int* in_sizes, int n_in,
                              void* d_out, int out_size) {
    const float* x     = (const float*)d_in[0];
    const void*  ei    = d_in[1];
    const float* W1    = (const float*)d_in[2];
    const float* b1    = (const float*)d_in[3];
    const float* W2    = (const float*)d_in[4];
    const float* b2    = (const float*)d_in[5];
    const float* gamma = (const float*)d_in[6];
    const float* beta  = (const float*)d_in[7];
    const float* Wc    = (const float*)d_in[8];
    const float* bc    = (const float*)d_in[9];
    float*       out   = (float*)d_out;

    cudaFuncSetAttribute(gemm_mma_kernel<0>, cudaFuncAttributeMaxDynamicSharedMemorySize, SMEM_GEMM_BYTES);
    cudaFuncSetAttribute(gemm_mma_kernel<1>, cudaFuncAttributeMaxDynamicSharedMemorySize, SMEM_GEMM_BYTES);

    // 1) zero counts + BN sums ; detect ei dtype
    init_kernel<<<(N_NODES + 255) / 256, 256>>>((const long long*)ei);

    // 2) CSR build: count -> scan -> fill
    count_kernel<<<N_EDGES / 256, 256>>>(ei);
    scan_kernel<<<1, SCAN_T>>>();
    fill_kernel<<<N_EDGES / 256, 256>>>(ei);

    // 2b) weights -> fp16 B-fragment layout
    tr_both_kernel<<<(W1_F4 + W2_F4) / 256, 256>>>(W1, W2);

    // 3) gather: agg = x + neighbor sum  (no float atomics)
    gather_kernel<<<N_NODES / 8, 256>>>(x);

    // 4) h1(frag fp16) = relu(agg @ W1 + b1)
    dim3 gg(MBLKS, HIDDEN / 128);
    gemm_mma_kernel<0><<<gg, 128, SMEM_GEMM_BYTES>>>(b1);

    // 5) h2(fp32) = h1 @ W2 + b2  (+ fused BN column sums)
    gemm_mma_kernel<1><<<gg, 128, SMEM_GEMM_BYTES>>>(b2);

    // 6) BN finalize
    bn_finalize_kernel<<<1, HIDDEN>>>(gamma, beta);

    // 7) out = relu(BN(h2)) @ Wc + bc
    cls_kernel<<<N_NODES / 8, 256>>>(Wc, bc, out);
}

// round 16
// speedup vs baseline: 1.3213x; 1.3213x over previous
#include <cuda_runtime.h>
#include <cuda_fp16.h>
#include <cstdint>

#define N_NODES   50000
#define NUM_FEAT  64
#define HIDDEN    512
#define N_EDGES   800000
#define BN_EPS    1e-5f
#define MBLKS     782                   // ceil(50000/64)

// ================= helpers =================
__device__ __forceinline__ uint32_t smem_u32(const void* p) {
    uint32_t a;
    asm("{ .reg .u64 t; cvta.to.shared.u64 t, %1; cvt.u32.u64 %0, t; }" : "=r"(a) : "l"(p));
    return a;
}
__device__ __forceinline__ uint32_t pack_h2(float lo, float hi) {
    __half2 h = __floats2half2_rn(lo, hi);
    return *reinterpret_cast<uint32_t*>(&h);
}
__device__ __forceinline__ void mma_f16(float* d, const uint32_t* a, const uint32_t* b) {
    asm volatile("mma.sync.aligned.m16n8k16.row.col.f32.f16.f16.f32 "
        "{%0,%1,%2,%3}, {%4,%5,%6,%7}, {%8,%9}, {%0,%1,%2,%3};"
        : "+f"(d[0]), "+f"(d[1]), "+f"(d[2]), "+f"(d[3])
        : "r"(a[0]), "r"(a[1]), "r"(a[2]), "r"(a[3]), "r"(b[0]), "r"(b[1]));
}
__device__ __forceinline__ void cp_async16(uint32_t dst, const void* src, int src_bytes) {
    asm volatile("cp.async.cg.shared.global [%0], [%1], 16, %2;"
                 :: "r"(dst), "l"(src), "r"(src_bytes) : "memory");
}
#define CP_COMMIT() asm volatile("cp.async.commit_group;" ::: "memory")

// ================= scratch (static device globals) =================
__device__ float g_agg[(size_t)N_NODES * NUM_FEAT];        // 12.8 MB fp32
__device__ uint4 g_h1f[(size_t)MBLKS * 16 * 256];          // 51.2 MB fp16 A-fragments
__device__ float g_h2 [(size_t)N_NODES * HIDDEN];          // 102.4 MB row-major fp32
__device__ uint4 g_w1f[4 * 2 * 512];                       // W1 fp16 B-fragments
__device__ uint4 g_w2f[4 * 16 * 512];                      // W2 fp16 B-fragments
__device__ float g_sum  [HIDDEN];
__device__ float g_sumsq[HIDDEN];
__device__ float g_scale[HIDDEN];
__device__ float g_shift[HIDDEN];
__device__ int   g_idx64;

// ================= init: agg = x, zero BN accumulators, detect ei dtype ======
__global__ void init_kernel(const float* __restrict__ x, const long long* __restrict__ ei) {
    int i = blockIdx.x * blockDim.x + threadIdx.x;
    ((float4*)g_agg)[i] = ((const float4*)x)[i];
    if (i < HIDDEN) { g_sum[i] = 0.f; g_sumsq[i] = 0.f; }
    if (i == 0) {
        int is64 = 1;
        for (int k = 0; k < 64; k++) {
            long long v = ei[k];
            if (v < 0 || v >= N_NODES) { is64 = 0; break; }
        }
        g_idx64 = is64;
    }
}

// ================= edge aggregation: agg[dst] += x[src] =================
__global__ void agg_kernel(const float* __restrict__ x, const void* __restrict__ ei_raw) {
    int g = blockIdx.x * blockDim.x + threadIdx.x;
    int e = g >> 4;
    int c = (g & 15) << 2;
    if (e >= N_EDGES) return;
    int src, dst;
    if (g_idx64) {
        const long long* ei = (const long long*)ei_raw;
        src = (int)ei[e];
        dst = (int)ei[N_EDGES + e];
    } else {
        const int* ei = (const int*)ei_raw;
        src = ei[e];
        dst = ei[N_EDGES + e];
    }
    if ((unsigned)src >= N_NODES || (unsigned)dst >= N_NODES) return;
    float4 v = *(const float4*)&x[src * NUM_FEAT + c];
    float* d = &g_agg[dst * NUM_FEAT + c];
    asm volatile("red.global.add.v4.f32 [%0], {%1, %2, %3, %4};"
                 :: "l"(d), "f"(v.x), "f"(v.y), "f"(v.z), "f"(v.w) : "memory");
}

// ================= weights -> fp16 B-fragment layout =================
template<int KR>
__device__ __forceinline__ void tr_one(const float* __restrict__ W, uint4* dst, int g) {
    constexpr int S = KR / 32;
    int nb = g / (S * 512);
    int rem = g % (S * 512);
    int stage = rem >> 9;
    int i4 = rem & 511;
    int lane = i4 & 31, nip = (i4 >> 5) & 3, wn = (i4 >> 7) & 1, kk = (i4 >> 8) & 1;
    int colx = nb * 128 + wn * 64 + nip * 16 + (lane >> 2);
    int colz = colx + 8;
    int kc = stage * 32 + kk * 16 + (lane & 3) * 2;
    uint4 v;
    v.x = pack_h2(W[(size_t)kc * HIDDEN + colx],       W[(size_t)(kc + 1) * HIDDEN + colx]);
    v.y = pack_h2(W[(size_t)(kc + 8) * HIDDEN + colx], W[(size_t)(kc + 9) * HIDDEN + colx]);
    v.z = pack_h2(W[(size_t)kc * HIDDEN + colz],       W[(size_t)(kc + 1) * HIDDEN + colz]);
    v.w = pack_h2(W[(size_t)(kc + 8) * HIDDEN + colz], W[(size_t)(kc + 9) * HIDDEN + colz]);
    dst[g] = v;
}
#define W1_F4 (4 * 2 * 512)            // 4096
#define W2_F4 (4 * 16 * 512)           // 32768
__global__ void tr_both_kernel(const float* __restrict__ W1, const float* __restrict__ W2) {
    int g = blockIdx.x * 256 + threadIdx.x;
    if (g < W1_F4) tr_one<NUM_FEAT>(W1, g_w1f, g);
    else           tr_one<HIDDEN>(W2, g_w2f, g - W1_F4);
}

// ================= fp16 mma.sync GEMM =================
// MODE 0: h1(frag fp16) = relu(g_agg(fp32) @ W1 + b1)     3-stage (S=2)
// MODE 1: h2(fp32 rowmaj) = h1(frag) @ W2 + b2  + BN stats  4-stage (S=16)
// Block 64x128, BK=32 (2 x k16), 4 warps (2Mx2N) of 32x64.
#define BBUF_U4 512                     // uint4 per B stage (8 KB)
#define SMEM_GEMM_BYTES 49152

template<int MODE>
__global__ __launch_bounds__(128, 4)
void gemm_mma_kernel(const float* __restrict__ bias) {
    constexpr int M = N_NODES;
    constexpr int K = (MODE == 0) ? NUM_FEAT : HIDDEN;
    constexpr int S = K / 32;                 // 2 or 16
    constexpr int NS = (MODE == 0) ? 3 : 4;   // pipeline stages
    constexpr int ABUF_F = (MODE == 0) ? 2048 : 1024;   // floats per A stage

    extern __shared__ float sm[];
    float* Asm  = sm;                               // NS x A stage
    uint4* Bsm  = (uint4*)(sm + NS * ABUF_F);       // NS x 512 uint4

    const int tid  = threadIdx.x;
    const int lane = tid & 31;
    const int wid  = tid >> 5;
    const int wm   = wid >> 1;       // 0..1
    const int wn   = wid & 1;        // 0..1
    const int mblk = blockIdx.x;
    const int m0   = mblk * 64;
    const int nb   = blockIdx.y;

    auto issue = [&](int s) {
        const int buf = s % NS;
        if (MODE == 0) {
            float* Ab = Asm + buf * ABUF_F;
            const int k0 = s * 32;
            #pragma unroll
            for (int i = 0; i < 4; i++) {
                int idx = tid + i * 128;
                int r = idx >> 3, g4 = idx & 7;
                int row = m0 + r;
                bool v = row < M;
                long long rc = v ? row : (M - 1);
                int sg = (g4 ^ (r & 7)) << 2;
                cp_async16(smem_u32(&Ab[r * 32 + sg]), &g_agg[rc * (long long)K + k0 + g4 * 4], v ? 16 : 0);
            }
        } else {
            uint4* Ab = (uint4*)(Asm + buf * ABUF_F);       // 256 uint4
            const uint4* asrc = g_h1f + ((size_t)mblk * 16 + s) * 256;
            #pragma unroll
            for (int i = 0; i < 2; i++) {
                int idx = tid + i * 128;
                cp_async16(smem_u32(&Ab[idx]), asrc + idx, 16);
            }
        }
        uint4* Bb = Bsm + buf * BBUF_U4;
        const uint4* src = ((MODE == 0) ? g_w1f : g_w2f) + ((size_t)nb * S + s) * BBUF_U4;
        #pragma unroll
        for (int i = 0; i < 4; i++) {
            int idx = tid + i * 128;
            cp_async16(smem_u32(&Bb[idx]), src + idx, 16);
        }
        CP_COMMIT();
    };

    float acc[2][8][4];
    #pragma unroll
    for (int mi = 0; mi < 2; mi++)
        #pragma unroll
        for (int ni = 0; ni < 8; ni++)
            #pragma unroll
            for (int j = 0; j < 4; j++) acc[mi][ni][j] = 0.f;

    issue(0);
    if (S > 1) issue(1);
    if (NS == 4 && S > 2) issue(2);

    #pragma unroll 1
    for (int s = 0; s < S; s++) {
        if (NS == 4 && s + 2 < S)  asm volatile("cp.async.wait_group 2;" ::: "memory");
        else if (s + 1 < S)        asm volatile("cp.async.wait_group 1;" ::: "memory");
        else                       asm volatile("cp.async.wait_group 0;" ::: "memory");
        __syncthreads();
        const int buf = s % NS;
        const float* Abf = Asm + buf * ABUF_F;
        const uint4* Ab4 = (const uint4*)Abf;
        const uint4* Bb  = Bsm + buf * BBUF_U4;

        #pragma unroll
        for (int kk = 0; kk < 2; kk++) {
            uint32_t a[2][4];
            if (MODE == 0) {
                const int kcl = kk * 16 + (lane & 3) * 2;
                const int g4a = kcl >> 2, offa = kcl & 3;
                const int g4b = (kcl + 8) >> 2, offb = (kcl + 8) & 3;
                #pragma unroll
                for (int mi = 0; mi < 2; mi++) {
                    int r  = wm * 32 + mi * 16 + (lane >> 2);
                    int sw = r & 7;
                    float2 f0 = *(const float2*)&Abf[r * 32 + ((g4a ^ sw) << 2) + offa];
                    float2 f1 = *(const float2*)&Abf[(r + 8) * 32 + ((g4a ^ sw) << 2) + offa];
                    float2 f2 = *(const float2*)&Abf[r * 32 + ((g4b ^ sw) << 2) + offb];
                    float2 f3 = *(const float2*)&Abf[(r + 8) * 32 + ((g4b ^ sw) << 2) + offb];
                    a[mi][0] = pack_h2(f0.x, f0.y);
                    a[mi][1] = pack_h2(f1.x, f1.y);
                    a[mi][2] = pack_h2(f2.x, f2.y);
                    a[mi][3] = pack_h2(f3.x, f3.y);
                }
            } else {
                #pragma unroll
                for (int mi = 0; mi < 2; mi++) {
                    int grp = wm * 2 + mi;
                    uint4 av = Ab4[(kk * 4 + grp) * 32 + lane];
                    a[mi][0] = av.x; a[mi][1] = av.y; a[mi][2] = av.z; a[mi][3] = av.w;
                }
            }
            uint32_t b[8][2];
            #pragma unroll
            for (int nip = 0; nip < 4; nip++) {
                uint4 bv = Bb[((kk * 2 + wn) * 4 + nip) * 32 + lane];
                b[nip * 2][0]     = bv.x;  b[nip * 2][1]     = bv.y;
                b[nip * 2 + 1][0] = bv.z;  b[nip * 2 + 1][1] = bv.w;
            }
            #pragma unroll
            for (int mi = 0; mi < 2; mi++)
                #pragma unroll
                for (int ni = 0; ni < 8; ni++)
                    mma_f16(acc[mi][ni], a[mi], b[ni]);
        }
        if (s + NS - 1 < S) issue(s + NS - 1);
    }

    const int n0 = nb * 128;

    if (MODE == 0) {
        // ---- epilogue: bias+relu -> fp16 A-fragments, direct from registers ----
        #pragma unroll
        for (int mi = 0; mi < 2; mi++) {
            const int grp = wm * 2 + mi;
            #pragma unroll
            for (int j = 0; j < 4; j++) {
                const int c0 = wn * 64 + (2 * j) * 8 + (lane & 3) * 2;
                const float bx0 = __ldg(&bias[n0 + c0]);
                const float by0 = __ldg(&bias[n0 + c0 + 1]);
                const float bx1 = __ldg(&bias[n0 + c0 + 8]);
                const float by1 = __ldg(&bias[n0 + c0 + 9]);
                uint4 v;
                v.x = pack_h2(fmaxf(acc[mi][2 * j][0] + bx0, 0.f),
                              fmaxf(acc[mi][2 * j][1] + by0, 0.f));
                v.y = pack_h2(fmaxf(acc[mi][2 * j][2] + bx0, 0.f),
                              fmaxf(acc[mi][2 * j][3] + by0, 0.f));
                v.z = pack_h2(fmaxf(acc[mi][2 * j + 1][0] + bx1, 0.f),
                              fmaxf(acc[mi][2 * j + 1][1] + by1, 0.f));
                v.w = pack_h2(fmaxf(acc[mi][2 * j + 1][2] + bx1, 0.f),
                              fmaxf(acc[mi][2 * j + 1][3] + by1, 0.f));
                const int sl = wn * 2 + (j >> 1);
                const int kkd = j & 1;
                g_h1f[((size_t)mblk * 16 + nb * 4 + sl) * 256 + (kkd * 4 + grp) * 32 + lane] = v;
            }
        }
    } else {
        // ---- epilogue: bias -> row-major fp32 h2 + fused BN column stats ----
        float scv[16], sqv[16];
        #pragma unroll
        for (int i = 0; i < 16; i++) { scv[i] = 0.f; sqv[i] = 0.f; }
        #pragma unroll
        for (int mi = 0; mi < 2; mi++) {
            const int r0 = m0 + wm * 32 + mi * 16 + (lane >> 2);
            #pragma unroll
            for (int ni = 0; ni < 8; ni++) {
                const int col = n0 + wn * 64 + ni * 8 + (lane & 3) * 2;
                const float bx = __ldg(&bias[col]);
                const float by = __ldg(&bias[col + 1]);
                float2 v;
                if (r0 < M) {
                    v.x = acc[mi][ni][0] + bx;
                    v.y = acc[mi][ni][1] + by;
                    scv[ni * 2]     += v.x;  sqv[ni * 2]     = fmaf(v.x, v.x, sqv[ni * 2]);
                    scv[ni * 2 + 1] += v.y;  sqv[ni * 2 + 1] = fmaf(v.y, v.y, sqv[ni * 2 + 1]);
                    *(float2*)&g_h2[(size_t)r0 * HIDDEN + col] = v;
                }
                if (r0 + 8 < M) {
                    v.x = acc[mi][ni][2] + bx;
                    v.y = acc[mi][ni][3] + by;
                    scv[ni * 2]     += v.x;  sqv[ni * 2]     = fmaf(v.x, v.x, sqv[ni * 2]);
                    scv[ni * 2 + 1] += v.y;  sqv[ni * 2 + 1] = fmaf(v.y, v.y, sqv[ni * 2 + 1]);
                    *(float2*)&g_h2[(size_t)(r0 + 8) * HIDDEN + col] = v;
                }
            }
        }
        #pragma unroll
        for (int i = 0; i < 16; i++) {
            #pragma unroll
            for (int off = 16; off >= 4; off >>= 1) {
                scv[i] += __shfl_down_sync(0xFFFFFFFFu, scv[i], off);
                sqv[i] += __shfl_down_sync(0xFFFFFFFFu, sqv[i], off);
            }
        }
        if (lane < 4) {
            #pragma unroll
            for (int i = 0; i < 16; i++) {
                int col = n0 + wn * 64 + (i >> 1) * 8 + lane * 2 + (i & 1);
                atomicAdd(&g_sum[col], scv[i]);
                atomicAdd(&g_sumsq[col], sqv[i]);
            }
        }
    }
}

// ================= BN finalize =================
__global__ void bn_finalize_kernel(const float* __restrict__ gamma,
                                   const float* __restrict__ beta) {
    int c = threadIdx.x;
    float inv_n = 1.0f / (float)N_NODES;
    float mean = g_sum[c] * inv_n;
    float var  = g_sumsq[c] * inv_n - mean * mean;
    float sc   = gamma[c] * rsqrtf(var + BN_EPS);
    g_scale[c] = sc;
    g_shift[c] = beta[c] - mean * sc;
}

// ================= fused BN-apply + ReLU + classifier =================
__global__ __launch_bounds__(256)
void cls_kernel(const float* __restrict__ Wc, const float* __restrict__ bc,
                float* __restrict__ out) {
    __shared__ float s_scale[HIDDEN], s_shift[HIDDEN], s_w0[HIDDEN], s_w1[HIDDEN];
    int tid = threadIdx.x;
    for (int c = tid; c < HIDDEN; c += 256) {
        s_scale[c] = g_scale[c];
        s_shift[c] = g_shift[c];
        s_w0[c] = Wc[c * 2 + 0];
        s_w1[c] = Wc[c * 2 + 1];
    }
    __syncthreads();

    int warp = tid >> 5, lane = tid & 31;
    int row = blockIdx.x * 8 + warp;
    const float4* h = (const float4*)&g_h2[(long long)row * HIDDEN];
    float a0 = 0.f, a1 = 0.f;
    #pragma unroll
    for (int it = 0; it < 4; it++) {
        int c4 = it * 32 + lane;
        float4 v = h[c4];
        int c = c4 * 4;
        float t;
        t = fmaxf(fmaf(v.x, s_scale[c + 0], s_shift[c + 0]), 0.f);
        a0 = fmaf(t, s_w0[c + 0], a0); a1 = fmaf(t, s_w1[c + 0], a1);
        t = fmaxf(fmaf(v.y, s_scale[c + 1], s_shift[c + 1]), 0.f);
        a0 = fmaf(t, s_w0[c + 1], a0); a1 = fmaf(t, s_w1[c + 1], a1);
        t = fmaxf(fmaf(v.z, s_scale[c + 2], s_shift[c + 2]), 0.f);
        a0 = fmaf(t, s_w0[c + 2], a0); a1 = fmaf(t, s_w1[c + 2], a1);
        t = fmaxf(fmaf(v.w, s_scale[c + 3], s_shift[c + 3]), 0.f);
        a0 = fmaf(t, s_w0[c + 3], a0); a1 = fmaf(t, s_w1[c + 3], a1);
    }
    #pragma unroll
    for (int o = 16; o > 0; o >>= 1) {
        a0 += __shfl_down_sync(0xFFFFFFFFu, a0, o);
        a1 += __shfl_down_sync(0xFFFFFFFFu, a1, o);
    }
    if (lane == 0) {
        out[row * 2 + 0] = a0 + bc[0];
        out[row * 2 + 1] = a1 + bc[1];
    }
}

// ================= launch =================
extern "C" void kernel_launch(void* const* d_in, const int* in_sizes, int n_in,
                              void* d_out, int out_size) {
    const float* x     = (const float*)d_in[0];
    const void*  ei    = d_in[1];
    const float* W1    = (const float*)d_in[2];
    const float* b1    = (const float*)d_in[3];
    const float* W2    = (const float*)d_in[4];
    const float* b2    = (const float*)d_in[5];
    const float* gamma = (const float*)d_in[6];
    const float* beta  = (const float*)d_in[7];
    const float* Wc    = (const float*)d_in[8];
    const float* bc    = (const float*)d_in[9];
    float*       out   = (float*)d_out;

    cudaFuncSetAttribute(gemm_mma_kernel<0>, cudaFuncAttributeMaxDynamicSharedMemorySize, SMEM_GEMM_BYTES);
    cudaFuncSetAttribute(gemm_mma_kernel<1>, cudaFuncAttributeMaxDynamicSharedMemorySize, SMEM_GEMM_BYTES);

    // 1) agg = x ; zero BN accumulators ; detect ei dtype
    init_kernel<<<(N_NODES * NUM_FEAT / 4) / 256, 256>>>(x, (const long long*)ei);

    // 2) agg[dst] += x[src]   (vector red)
    agg_kernel<<<(N_EDGES * 16) / 256, 256>>>(x, ei);

    // 2b) weights -> fp16 B-fragment layout
    tr_both_kernel<<<(W1_F4 + W2_F4) / 256, 256>>>(W1, W2);

    // 3) h1(frag fp16) = relu(agg @ W1 + b1)
    dim3 gg(MBLKS, HIDDEN / 128);
    gemm_mma_kernel<0><<<gg, 128, SMEM_GEMM_BYTES>>>(b1);

    // 4) h2(fp32) = h1 @ W2 + b2  (+ fused BN column sums)
    gemm_mma_kernel<1><<<gg, 128, SMEM_GEMM_BYTES>>>(b2);

    // 5) BN finalize
    bn_finalize_kernel<<<1, HIDDEN>>>(gamma, beta);

    // 6) out = relu(BN(h2)) @ Wc + bc
    cls_kernel<<<N_NODES / 8, 256>>>(Wc, bc, out);
}